// round 7
// baseline (speedup 1.0000x reference)
#include <cuda_runtime.h>
#include <cuda_bf16.h>

// Problem shape (fixed by the dataset)
constexpr int N  = 64;
constexpr int C  = 256;
constexpr int S  = 30;
constexpr int HW = 176;               // h*w = 16*11, contiguous innermost
constexpr int CSTRIDE = S * HW;       // 5280
constexpr int NSTRIDE = C * CSTRIDE;  // 1351680
constexpr int R  = 8;                 // conv radius: g[8] ~ 9e-10, below fp32 noise
constexpr int TOPK = 10;

// Scratch: stability scores, same layout as seqs [n, c, s, h*w]
__device__ float d_score[(long long)N * C * S * HW];
// Real-space low-pass kernel coefficients g[0..R]
__device__ float d_g[R + 1];

// ---------------------------------------------------------------------------
// Kernel 1: compute exact conv coefficients in double precision.
// g[d] = (1/256) * ( mask[0] + mask[128]*cos(pi*d) + 2*sum_{k=1..127} mask[k]*cos(2*pi*k*d/256) )
// mask[k] = exp(-0.5*(k/32)^2)   (freq_axis = k/128, sigma = 0.25 -> k/32)
// ---------------------------------------------------------------------------
__global__ void kinit() {
    const int d    = threadIdx.x >> 5;   // 0..R (one warp per coefficient)
    const int lane = threadIdx.x & 31;
    if (d > R) return;
    const double PI = 3.14159265358979323846;
    double part = 0.0;
    for (int k = 1 + lane; k <= 127; k += 32) {
        double fk = (double)k / 32.0;
        part += 2.0 * exp(-0.5 * fk * fk) * cos(PI * (double)k * (double)d / 128.0);
    }
    #pragma unroll
    for (int o = 16; o; o >>= 1)
        part += __shfl_down_sync(0xffffffffu, part, o);
    if (lane == 0) {
        double nyq = exp(-8.0) * ((d & 1) ? -1.0 : 1.0);   // mask[128]*cos(pi*d)
        d_g[d] = (float)((part + 1.0 + nyq) / 256.0);      // mask[0] = 1
    }
}

// ---------------------------------------------------------------------------
// Kernel 2: circular conv along c + stability score.
// Block = (hw-tile of 32, s, n). Smem tile [256][32], conflict-free
// (row stride = 32 banks -> lane maps to bank). 8 warps: warp w computes
// channels [32w, 32w+32) via a 48-value register window.
// ---------------------------------------------------------------------------
__global__ void __launch_bounds__(256) kconv(const float* __restrict__ seqs) {
    const int hw0 = blockIdx.x * 32;
    const int s   = blockIdx.y;
    const int n   = blockIdx.z;
    const int tw  = min(32, HW - hw0);   // 32 or 16 (last tile)

    __shared__ float X[256][32];

    const int lane = threadIdx.x & 31;
    const int wid  = threadIdx.x >> 5;
    const int base = n * NSTRIDE + s * HW + hw0;
    const bool act = lane < tw;

    // Load tile: each warp loads rows c ≡ wid (mod 8); lane = hw -> 128B coalesced
    #pragma unroll
    for (int i = 0; i < 32; ++i) {
        int c = (i << 3) + wid;
        X[c][lane] = act ? __ldg(&seqs[base + c * CSTRIDE + lane]) : 0.0f;
    }
    __syncthreads();

    float g[R + 1];
    #pragma unroll
    for (int d = 0; d <= R; ++d) g[d] = d_g[d];

    if (!act) return;

    const int c0 = wid << 5;
    float xv[32 + 2 * R];
    #pragma unroll
    for (int i = 0; i < 32 + 2 * R; ++i)
        xv[i] = X[(c0 - R + i) & 255][lane];

    #pragma unroll
    for (int j = 0; j < 32; ++j) {
        const float x  = xv[j + R];
        float acc = g[0] * x;
        #pragma unroll
        for (int d = 1; d <= R; ++d)
            acc = fmaf(g[d], xv[j + R - d] + xv[j + R + d], acc);
        const float denom = fabsf(acc - x) + 1e-6f;
        const float sc    = __fdividef(fabsf(acc), denom);
        d_score[base + (c0 + j) * CSTRIDE + lane] = sc;
    }
}

// ---------------------------------------------------------------------------
// Kernel 3: per-(n,c,hw) top-10 over s (stable tie-break = earliest s),
// mean of selected seqs, max-pool, sigmoid fusion.
// Block = one (n,c); thread = hw position; reads coalesced per s-row.
// ---------------------------------------------------------------------------
__global__ void __launch_bounds__(192) ktopk(const float* __restrict__ seqs,
                                             const float* __restrict__ fusion_logit,
                                             float* __restrict__ out) {
    const int t  = threadIdx.x;
    const int nc = blockIdx.x;
    if (t >= HW) return;
    const int base = nc * CSTRIDE + t;

    float v[S], sc[S];
    #pragma unroll
    for (int s = 0; s < S; ++s) {
        v[s]  = __ldg(&seqs[base + s * HW]);
        sc[s] = d_score[base + s * HW];
    }

    float maxv = v[0];
    #pragma unroll
    for (int s = 1; s < S; ++s) maxv = fmaxf(maxv, v[s]);

    // Top-10 scores via FMNMX insertion chain (scores are >= 0, so -1 is -inf)
    float top[TOPK];
    #pragma unroll
    for (int i = 0; i < TOPK; ++i) top[i] = -1.0f;
    #pragma unroll
    for (int s = 0; s < S; ++s) {
        float carry = sc[s];
        #pragma unroll
        for (int i = 0; i < TOPK; ++i) {
            float mx = fmaxf(top[i], carry);
            carry    = fminf(top[i], carry);
            top[i]   = mx;
        }
    }
    const float thr = top[TOPK - 1];

    // Accumulate: strictly greater first (at most 9), then earliest ties.
    // This reproduces jax.lax.top_k's stable (lowest-index-first) selection set.
    float sum = 0.0f;
    int taken = 0;
    #pragma unroll
    for (int s = 0; s < S; ++s)
        if (sc[s] > thr) { sum += v[s]; ++taken; }
    #pragma unroll
    for (int s = 0; s < S; ++s)
        if (sc[s] == thr && taken < TOPK) { sum += v[s]; ++taken; }

    const float lg    = fusion_logit[0];
    const float alpha = 1.0f / (1.0f + expf(-lg));
    out[nc * HW + t] = alpha * (sum * (1.0f / TOPK)) + (1.0f - alpha) * maxv;
}

// ---------------------------------------------------------------------------
extern "C" void kernel_launch(void* const* d_in, const int* in_sizes, int n_in,
                              void* d_out, int out_size) {
    const float* seqs  = (const float*)d_in[0];
    const float* logit = (const float*)d_in[1];
    float* out = (float*)d_out;

    kinit<<<1, (R + 1) * 32>>>();
    kconv<<<dim3((HW + 31) / 32, S, N), 256>>>(seqs);
    ktopk<<<N * C, 192>>>(seqs, logit, out);
}